// round 15
// baseline (speedup 1.0000x reference)
#include <cuda_runtime.h>
#include <cstdint>

#define BN  8
#define CIN 64
#define HH  56
#define WW  56
#define HW  (HH*WW)
#define OCM 128

typedef unsigned long long u64;

// Packed weight scratch: pairs (o, o+1) interleaved as float2, indexed [c][pair][tap].
__device__ float2 g_wp5 [CIN * 64 * 25];   // deform k5 weights
__device__ float2 g_wp3 [CIN * 64 * 9];    // deform k3 weights
__device__ float2 g_owp5[CIN * 40 * 25];   // offset k5 weights (75 och -> 40 pairs padded)
__device__ float2 g_owp3[CIN * 16 * 9];    // offset k3 weights (27 och -> 16 pairs padded)
__device__ float2 g_swp [CIN * 64];        // 1x1 residual weights

__device__ __forceinline__ u64 pack2(float lo, float hi) {
    u64 r; asm("mov.b64 %0, {%1, %2};" : "=l"(r) : "f"(lo), "f"(hi)); return r;
}
__device__ __forceinline__ void ffma2(u64 &d, u64 a, u64 b) {
    asm("fma.rn.f32x2 %0, %1, %2, %0;" : "+l"(d) : "l"(a), "l"(b));
}
__device__ __forceinline__ float2 unpack2(u64 v) {
    float2 f; asm("mov.b64 {%0, %1}, %2;" : "=f"(f.x), "=f"(f.y) : "l"(v)); return f;
}

// ---------------------------------------------------------------------------
// Prep: pack weights pair-interleaved, once per launch.
// ---------------------------------------------------------------------------
__global__ void prep_weights(const float* __restrict__ w3, const float* __restrict__ w5,
                             const float* __restrict__ sw,
                             const float* __restrict__ o3w, const float* __restrict__ o5w)
{
    int i = blockIdx.x * 256 + threadIdx.x;
    if (i < CIN * 64 * 25) {
        int c = i / (64 * 25), r = i - c * (64 * 25), p = r / 25, tap = r - p * 25;
        g_wp5[i] = make_float2(w5[(2 * p * CIN + c) * 25 + tap],
                               w5[((2 * p + 1) * CIN + c) * 25 + tap]);
    }
    if (i < CIN * 64 * 9) {
        int c = i / (64 * 9), r = i - c * (64 * 9), p = r / 9, tap = r - p * 9;
        g_wp3[i] = make_float2(w3[(2 * p * CIN + c) * 9 + tap],
                               w3[((2 * p + 1) * CIN + c) * 9 + tap]);
    }
    if (i < CIN * 40 * 25) {
        int c = i / (40 * 25), r = i - c * (40 * 25), p = r / 25, tap = r - p * 25;
        int o0 = 2 * p, o1 = o0 + 1;
        float a = (o0 < 75) ? o5w[(o0 * CIN + c) * 25 + tap] : 0.f;
        float b = (o1 < 75) ? o5w[(o1 * CIN + c) * 25 + tap] : 0.f;
        g_owp5[i] = make_float2(a, b);
    }
    if (i < CIN * 16 * 9) {
        int c = i / (16 * 9), r = i - c * (16 * 9), p = r / 9, tap = r - p * 9;
        int o0 = 2 * p, o1 = o0 + 1;
        float a = (o0 < 27) ? o3w[(o0 * CIN + c) * 9 + tap] : 0.f;
        float b = (o1 < 27) ? o3w[(o1 * CIN + c) * 9 + tap] : 0.f;
        g_owp3[i] = make_float2(a, b);
    }
    if (i < CIN * 64) {
        int c = i / 64, p = i - c * 64;
        g_swp[i] = make_float2(sw[2 * p * CIN + c], sw[(2 * p + 1) * CIN + c]);
    }
}

// ---------------------------------------------------------------------------
// Fused kernel: offset-conv(row y) -> stage A -> deform conv(row y).
// Weights read DIRECTLY from packed global buffers (warp-uniform broadcast
// LDG, L1-resident) -- no weight staging in smem. Smem (k5) ~47.7 KB ->
// bigger L1D carveout so the bilinear gather also becomes L1-hit.
// ---------------------------------------------------------------------------
template<int K, int CB>
__global__ void __launch_bounds__(256, 3) fused_kernel(
    const float* __restrict__ x,
    const float* __restrict__ ob,  const float* __restrict__ bias,
    const float* __restrict__ subb, float* __restrict__ out)
{
    constexpr int K2  = K * K;
    constexpr int P   = K / 2;
    constexpr int OCF = 3 * K2;
    constexpr int NPT = (((OCF + 1) / 2) + 7) & ~7;   // off och-pairs, padded
    constexpr int NP  = NPT / 8;
    constexpr int NPX = K2 * 56;
    constexpr int NIT = (NPX + 255) / 256;

    // smem layout (bytes)
    constexpr int SZA_OFF = 2 * K * 72 * 4;                  // oxs (2 bufs)
    constexpr int SZA_DEF = NPX * 20;                        // swt + pidx
    constexpr int SZA = ((SZA_OFF > SZA_DEF ? SZA_OFF : SZA_DEF) + 15) & ~15;
    constexpr int SZB_OFF = OCF * 64 * 4;                    // om_s
    constexpr int SZB_DEF = NPX * 8 + 64;                    // cols (2 bufs) + pad
    constexpr int SZB = ((SZB_OFF > SZB_DEF ? SZB_OFF : SZB_DEF) + 15) & ~15;
    constexpr int OFF_B = SZA;
    constexpr int OFF_C = SZA + SZB;                         // xrow (512 B)

    extern __shared__ __align__(16) char smem_raw[];

    const int b    = blockIdx.x / HH;
    const int y    = blockIdx.x % HH;
    const int tid  = threadIdx.x;
    const int lane = tid & 31;
    const int g    = tid >> 5;

    const float* xb = x + (size_t)b * CIN * HW;
    const float2* owp = (K == 3) ? (const float2*)g_owp3 : (const float2*)g_owp5;
    const float2* wp  = (K == 3) ? (const float2*)g_wp3  : (const float2*)g_wp5;

    // ======================= Phase 0: offset conv (row y) ==================
    {
        float* oxs  = (float*)smem_raw;                      // [2][K][72]
        float* om_s = (float*)(smem_raw + OFF_B);            // [OCF*64]

        u64 oacc[NP * 2] = {};

        auto ofill = [&](int c, int buf) {
            for (int i = tid; i < K * 72; i += 256) {
                int r = i / 72, col = i - r * 72;
                int yy = y - P + r, xx = col - P;
                float v = 0.f;
                if (yy >= 0 && yy < HH && xx >= 0 && xx < WW)
                    v = xb[c * HW + yy * WW + xx];
                oxs[buf * K * 72 + i] = v;
            }
        };

        ofill(0, 0);
        __syncthreads();

        for (int c = 0; c < CIN; c++) {
            int cur = c & 1;
            if (c + 1 < CIN) ofill(c + 1, cur ^ 1);

            const u64*  wrow = (const u64*)(owp + (c * NPT + g * NP) * K2);
            const float* xr  = oxs + cur * K * 72;
#pragma unroll
            for (int tap = 0; tap < K2; tap++) {
                int r = tap / K, dx = tap % K;
                float a0 = xr[r * 72 + lane + dx];
                float a1 = xr[r * 72 + lane + 32 + dx];
                u64 xa = pack2(a0, a0), xc = pack2(a1, a1);
#pragma unroll
                for (int j = 0; j < NP; j++) {
                    u64 wv = wrow[j * K2 + tap];     // uniform LDG broadcast
                    ffma2(oacc[2 * j],     xa, wv);
                    ffma2(oacc[2 * j + 1], xc, wv);
                }
            }
            __syncthreads();
        }

        // write offset-map row (with bias) into smem om_s
#pragma unroll
        for (int j = 0; j < NP; j++) {
            int o0 = (g * NP + j) * 2, o1 = o0 + 1;
            float2 v0 = unpack2(oacc[2 * j]);       // px lane    : (o0, o1)
            float2 v1 = unpack2(oacc[2 * j + 1]);   // px lane+32
            if (o0 < OCF) {
                float bb = ob[o0];
                om_s[o0 * 64 + lane]      = v0.x + bb;
                om_s[o0 * 64 + lane + 32] = v1.x + bb;
            }
            if (o1 < OCF) {
                float bb = ob[o1];
                om_s[o1 * 64 + lane]      = v0.y + bb;
                om_s[o1 * 64 + lane + 32] = v1.y + bb;
            }
        }
        __syncthreads();
    }

    // ======================= Stage A: sampling tables ======================
    float4*   swt  = (float4*)smem_raw;                    // [NPX]
    uint32_t* pidx = (uint32_t*)(smem_raw + NPX * 16);     // [NPX]
    {
        const float* om_s = (const float*)(smem_raw + OFF_B);
        for (int i = tid; i < NPX; i += 256) {
            int tap = i / 56, pxx = i - tap * 56;
            float dy = om_s[tap * 64 + pxx];
            float dx = om_s[(K2 + tap) * 64 + pxx];
            float ml = om_s[(2 * K2 + tap) * 64 + pxx];
            float m  = 1.f / (1.f + __expf(-ml));
            float sy = (float)(y   + tap / K - P) + dy;
            float sx = (float)(pxx + tap % K - P) + dx;
            float y0f = floorf(sy), x0f = floorf(sx);
            float ty = sy - y0f, tx = sx - x0f;
            int y0 = (int)y0f, x0 = (int)x0f, y1 = y0 + 1, x1 = x0 + 1;
            bool vy0 = (y0 >= 0) && (y0 < HH), vy1 = (y1 >= 0) && (y1 < HH);
            bool vx0 = (x0 >= 0) && (x0 < WW), vx1 = (x1 >= 0) && (x1 < WW);
            float w00 = (vy0 && vx0) ? (1.f - ty) * (1.f - tx) * m : 0.f;
            float w01 = (vy0 && vx1) ? (1.f - ty) * tx * m : 0.f;
            float w10 = (vy1 && vx0) ? ty * (1.f - tx) * m : 0.f;
            float w11 = (vy1 && vx1) ? ty * tx * m : 0.f;
            int cy0 = min(max(y0, 0), HH - 1);
            int cy1 = min(max(y1, 0), HH - 1);
            int cx0 = min(max(x0, 0), WW - 1);
            int cx1 = min(max(x1, 0), WW - 1);
            uint32_t bb  = (uint32_t)(cy0 * WW + cx0);
            uint32_t ddx = (uint32_t)(cx1 - cx0);            // 0 or 1
            uint32_t ddy = (uint32_t)((cy1 - cy0) * WW);     // 0 or 56
            swt [i] = make_float4(w00, w01, w10, w11);
            pidx[i] = bb | (ddx << 16) | (ddy << 18);
        }
    }
    __syncthreads();   // om_s fully consumed; region B is free now

    // ======================= Phase B: deform conv ==========================
    float* cols = (float*)(smem_raw + OFF_B);              // [2][NPX] (+pad slack)
    float* xrow = (float*)(smem_raw + OFF_C);              // [2][64]

    auto fill = [&](int c, int buf) {
        const float* Xc = xb + c * HW;
        float* cb = cols + buf * NPX;
#pragma unroll
        for (int it = 0; it < NIT; it++) {
            int i = tid + it * 256;
            if (i < NPX) {
                uint32_t pv = pidx[i];
                float4 wv = swt[i];
                int base = pv & 0xFFFF;
                int ddx  = (pv >> 16) & 3;
                int ddy  = pv >> 18;
                cb[i] = wv.x * Xc[base]       + wv.y * Xc[base + ddx]
                      + wv.z * Xc[base + ddy] + wv.w * Xc[base + ddy + ddx];
            }
        }
        if (tid < 64)
            xrow[buf * 64 + tid] = (tid < WW) ? Xc[y * WW + tid] : 0.f;
    };

    fill(0, 0);
    __syncthreads();

    u64 acc[16] = {};

    for (int c = 0; c < CIN; c++) {
        int cur = c & 1;
        if (c + 1 < CIN) fill(c + 1, cur ^ 1);

        const float* cc   = cols + cur * NPX;
        const u64*  wrow  = (const u64*)(wp + (c * 64 + g * 8) * K2);
#pragma unroll
        for (int tap = 0; tap < K2; tap++) {
            float c0 = cc[tap * 56 + lane];
            float c1 = cc[tap * 56 + lane + 32];   // lanes >= 24: discarded (slack keeps in-bounds)
            u64 xa = pack2(c0, c0), xc = pack2(c1, c1);
#pragma unroll
            for (int j = 0; j < 8; j++) {
                u64 wv = wrow[j * K2 + tap];       // uniform LDG broadcast
                ffma2(acc[2 * j],     xa, wv);
                ffma2(acc[2 * j + 1], xc, wv);
            }
        }
        // fused 1x1 residual
        {
            float s0 = xrow[cur * 64 + lane], s1 = xrow[cur * 64 + lane + 32];
            u64 xa = pack2(s0, s0), xc = pack2(s1, s1);
            const u64* srow = (const u64*)((const float2*)g_swp + c * 64 + g * 8);
#pragma unroll
            for (int j = 0; j < 8; j++) {
                u64 sv = srow[j];
                ffma2(acc[2 * j],     xa, sv);
                ffma2(acc[2 * j + 1], xc, sv);
            }
        }
        __syncthreads();
    }

#pragma unroll
    for (int j = 0; j < 8; j++) {
        int o0 = g * 16 + 2 * j, o1 = o0 + 1;
        float2 v0 = unpack2(acc[2 * j]);
        float2 v1 = unpack2(acc[2 * j + 1]);
        float bb0 = bias[o0] + subb[o0];
        float bb1 = bias[o1] + subb[o1];
        size_t base0 = ((size_t)b * (2 * OCM) + CB + o0) * HW + y * WW;
        size_t base1 = ((size_t)b * (2 * OCM) + CB + o1) * HW + y * WW;
        out[base0 + lane] = fmaxf(v0.x + bb0, 0.f);
        out[base1 + lane] = fmaxf(v0.y + bb1, 0.f);
        if (lane + 32 < WW) {
            out[base0 + lane + 32] = fmaxf(v1.x + bb0, 0.f);
            out[base1 + lane + 32] = fmaxf(v1.y + bb1, 0.f);
        }
    }
}

static constexpr int fused_smem(int K) {
    int K2 = K * K, OCF = 3 * K2, NPX = K2 * 56;
    int szA_off = 2 * K * 72 * 4;
    int szA_def = NPX * 20;
    int szA = ((szA_off > szA_def ? szA_off : szA_def) + 15) & ~15;
    int szB_off = OCF * 64 * 4;
    int szB_def = NPX * 8 + 64;
    int szB = ((szB_off > szB_def ? szB_off : szB_def) + 15) & ~15;
    return szA + szB + 512;
}

// ---------------------------------------------------------------------------
// Side stream + fork/join events (created once at load; no device allocation).
// ---------------------------------------------------------------------------
struct Aux {
    cudaStream_t s1;
    cudaEvent_t  fork, join;
    Aux() {
        cudaStreamCreateWithFlags(&s1, cudaStreamNonBlocking);
        cudaEventCreateWithFlags(&fork, cudaEventDisableTiming);
        cudaEventCreateWithFlags(&join, cudaEventDisableTiming);
    }
};
static Aux g_aux;

extern "C" void kernel_launch(void* const* d_in, const int* in_sizes, int n_in,
                              void* d_out, int out_size)
{
    const float* x   = (const float*)d_in[0];
    const float* w3  = (const float*)d_in[1];
    const float* b3  = (const float*)d_in[2];
    const float* o3w = (const float*)d_in[3];
    const float* o3b = (const float*)d_in[4];
    const float* w5  = (const float*)d_in[5];
    const float* b5  = (const float*)d_in[6];
    const float* o5w = (const float*)d_in[7];
    const float* o5b = (const float*)d_in[8];
    const float* sw  = (const float*)d_in[9];
    const float* sb  = (const float*)d_in[10];
    float* out = (float*)d_out;

    constexpr int SM3 = fused_smem(3);   // ~17.5 KB
    constexpr int SM5 = fused_smem(5);   // ~47.7 KB -> 3 blocks/SM, L1D ~85 KB
    cudaFuncSetAttribute((const void*)fused_kernel<3, 0>,
                         cudaFuncAttributeMaxDynamicSharedMemorySize, SM3);
    cudaFuncSetAttribute((const void*)fused_kernel<5, OCM>,
                         cudaFuncAttributeMaxDynamicSharedMemorySize, SM5);

    dim3 grid(BN * HH);

    prep_weights<<<(CIN * 64 * 25 + 255) / 256, 256>>>(w3, w5, sw, o3w, o5w);

    cudaEventRecord(g_aux.fork, 0);
    cudaStreamWaitEvent(g_aux.s1, g_aux.fork, 0);

    fused_kernel<3, 0  ><<<grid, 256, SM3, g_aux.s1>>>(x, o3b, b3, sb, out);
    fused_kernel<5, OCM><<<grid, 256, SM5>>>(x, o5b, b5, sb, out);

    cudaEventRecord(g_aux.join, g_aux.s1);
    cudaStreamWaitEvent(0, g_aux.join, 0);
}

// round 16
// speedup vs baseline: 1.4442x; 1.4442x over previous
#include <cuda_runtime.h>
#include <cstdint>

#define BN  8
#define CIN 64
#define HH  56
#define WW  56
#define HW  (HH*WW)
#define OCM 128

typedef unsigned long long u64;

// Pre-packed weights in the exact smem staging layout: [c][pair][tap] float2.
__device__ float2 g_wp5 [CIN * 64 * 25];   // deform k5
__device__ float2 g_wp3 [CIN * 64 * 9];    // deform k3
__device__ float2 g_owp5[CIN * 40 * 25];   // offset k5 (75 och -> 40 pairs, padded)
__device__ float2 g_owp3[CIN * 16 * 9];    // offset k3 (27 och -> 16 pairs, padded)
__device__ float2 g_swp [CIN * 64];        // 1x1 residual

__device__ __forceinline__ u64 pack2(float lo, float hi) {
    u64 r; asm("mov.b64 %0, {%1, %2};" : "=l"(r) : "f"(lo), "f"(hi)); return r;
}
__device__ __forceinline__ void ffma2(u64 &d, u64 a, u64 b) {
    asm("fma.rn.f32x2 %0, %1, %2, %0;" : "+l"(d) : "l"(a), "l"(b));
}
__device__ __forceinline__ float2 unpack2(u64 v) {
    float2 f; asm("mov.b64 {%0, %1}, %2;" : "=f"(f.x), "=f"(f.y) : "l"(v)); return f;
}

// ---------------------------------------------------------------------------
// Prep: pack weights pair-interleaved, once per launch (~6 us).
// ---------------------------------------------------------------------------
__global__ void prep_weights(const float* __restrict__ w3, const float* __restrict__ w5,
                             const float* __restrict__ sw,
                             const float* __restrict__ o3w, const float* __restrict__ o5w)
{
    int i = blockIdx.x * 256 + threadIdx.x;
    if (i < CIN * 64 * 25) {
        int c = i / (64 * 25), r = i - c * (64 * 25), p = r / 25, tap = r - p * 25;
        g_wp5[i] = make_float2(w5[(2 * p * CIN + c) * 25 + tap],
                               w5[((2 * p + 1) * CIN + c) * 25 + tap]);
    }
    if (i < CIN * 64 * 9) {
        int c = i / (64 * 9), r = i - c * (64 * 9), p = r / 9, tap = r - p * 9;
        g_wp3[i] = make_float2(w3[(2 * p * CIN + c) * 9 + tap],
                               w3[((2 * p + 1) * CIN + c) * 9 + tap]);
    }
    if (i < CIN * 40 * 25) {
        int c = i / (40 * 25), r = i - c * (40 * 25), p = r / 25, tap = r - p * 25;
        int o0 = 2 * p, o1 = o0 + 1;
        float a = (o0 < 75) ? o5w[(o0 * CIN + c) * 25 + tap] : 0.f;
        float b = (o1 < 75) ? o5w[(o1 * CIN + c) * 25 + tap] : 0.f;
        g_owp5[i] = make_float2(a, b);
    }
    if (i < CIN * 16 * 9) {
        int c = i / (16 * 9), r = i - c * (16 * 9), p = r / 9, tap = r - p * 9;
        int o0 = 2 * p, o1 = o0 + 1;
        float a = (o0 < 27) ? o3w[(o0 * CIN + c) * 9 + tap] : 0.f;
        float b = (o1 < 27) ? o3w[(o1 * CIN + c) * 9 + tap] : 0.f;
        g_owp3[i] = make_float2(a, b);
    }
    if (i < CIN * 64) {
        int c = i / 64, p = i - c * 64;
        g_swp[i] = make_float2(sw[2 * p * CIN + c], sw[(2 * p + 1) * CIN + c]);
    }
}

// ---------------------------------------------------------------------------
// Fused kernel (R10 structure): offset-conv(row y) -> stage A -> deform conv.
// One block per (b, y): 448 blocks, 256 threads, 3 blocks/SM.
// Weight smem fills are contiguous float4 copies from the packed globals.
// ---------------------------------------------------------------------------
template<int K, int CB>
__global__ void __launch_bounds__(256, 3) fused_kernel(
    const float* __restrict__ x,
    const float* __restrict__ ob,  const float* __restrict__ bias,
    const float* __restrict__ subb, float* __restrict__ out)
{
    constexpr int K2  = K * K;
    constexpr int P   = K / 2;
    constexpr int OCF = 3 * K2;
    constexpr int NPT = (((OCF + 1) / 2) + 7) & ~7;   // off och-pairs, padded to 8
    constexpr int NP  = NPT / 8;                      // off pairs per warp
    constexpr int NPX = K2 * 56;
    constexpr int NIT = (NPX + 255) / 256;
    constexpr int WV4 = 64 * K2 / 2;                  // deform weight float4s
    constexpr int OV4 = NPT * K2 / 2;                 // offset weight float4s

    // smem layout (bytes) -- R10 recipe (+64B overread pad)
    constexpr int SZA_OFF = NPT * K2 * 16 + 2 * K * 72 * 4;  // ows2 + oxs
    constexpr int SZA_DEF = NPX * 20;                        // swt + pidx
    constexpr int SZA = ((SZA_OFF > SZA_DEF ? SZA_OFF : SZA_DEF) + 15) & ~15;
    constexpr int SZB_OFF = OCF * 64 * 4;                    // om_s
    constexpr int SZB_DEF = 64 * K2 * 16 + NPX * 8 + 64;     // ws2 + cols + pad
    constexpr int SZB = ((SZB_OFF > SZB_DEF ? SZB_OFF : SZB_DEF) + 15) & ~15;
    constexpr int OFF_B = SZA;
    constexpr int OFF_C = SZA + SZB;

    extern __shared__ __align__(16) char smem_raw[];

    const int b    = blockIdx.x / HH;
    const int y    = blockIdx.x % HH;
    const int tid  = threadIdx.x;
    const int lane = tid & 31;
    const int g    = tid >> 5;

    const float* xb = x + (size_t)b * CIN * HW;
    const float2* owp = (K == 3) ? (const float2*)g_owp3 : (const float2*)g_owp5;
    const float2* wp  = (K == 3) ? (const float2*)g_wp3  : (const float2*)g_wp5;

    // ======================= Phase 0: offset conv (row y) ==================
    {
        float2* ows2 = (float2*)smem_raw;                        // [2][NPT*K2]
        float*  oxs  = (float*)(smem_raw + NPT * K2 * 16);       // [2][K][72]
        float*  om_s = (float*)(smem_raw + OFF_B);               // [OCF*64]

        u64 oacc[NP * 2] = {};

        auto ofill = [&](int c, int buf) {
            // vectorized contiguous weight copy
            float4* dst = (float4*)(ows2 + buf * NPT * K2);
            const float4* src = (const float4*)(owp + c * NPT * K2);
#pragma unroll
            for (int it = 0; it < (OV4 + 255) / 256; it++) {
                int i = tid + it * 256;
                if (i < OV4) dst[i] = src[i];
            }
            for (int i = tid; i < K * 72; i += 256) {
                int r = i / 72, col = i - r * 72;
                int yy = y - P + r, xx = col - P;
                float v = 0.f;
                if (yy >= 0 && yy < HH && xx >= 0 && xx < WW)
                    v = xb[c * HW + yy * WW + xx];
                oxs[buf * K * 72 + i] = v;
            }
        };

        ofill(0, 0);
        __syncthreads();

        for (int c = 0; c < CIN; c++) {
            int cur = c & 1;
            if (c + 1 < CIN) ofill(c + 1, cur ^ 1);

            const u64*  wrow = (const u64*)(ows2 + cur * NPT * K2) + g * NP * K2;
            const float* xr  = oxs + cur * K * 72;
#pragma unroll
            for (int tap = 0; tap < K2; tap++) {
                int r = tap / K, dx = tap % K;
                float a0 = xr[r * 72 + lane + dx];
                float a1 = xr[r * 72 + lane + 32 + dx];
                u64 xa = pack2(a0, a0), xc = pack2(a1, a1);
#pragma unroll
                for (int j = 0; j < NP; j++) {
                    u64 wv = wrow[j * K2 + tap];
                    ffma2(oacc[2 * j],     xa, wv);
                    ffma2(oacc[2 * j + 1], xc, wv);
                }
            }
            __syncthreads();
        }

        // write offset-map row (with bias) into smem om_s
#pragma unroll
        for (int j = 0; j < NP; j++) {
            int o0 = (g * NP + j) * 2, o1 = o0 + 1;
            float2 v0 = unpack2(oacc[2 * j]);       // px lane    : (o0, o1)
            float2 v1 = unpack2(oacc[2 * j + 1]);   // px lane+32
            if (o0 < OCF) {
                float bb = ob[o0];
                om_s[o0 * 64 + lane]      = v0.x + bb;
                om_s[o0 * 64 + lane + 32] = v1.x + bb;
            }
            if (o1 < OCF) {
                float bb = ob[o1];
                om_s[o1 * 64 + lane]      = v0.y + bb;
                om_s[o1 * 64 + lane + 32] = v1.y + bb;
            }
        }
        __syncthreads();
    }

    // ======================= Stage A: sampling tables ======================
    float4*   swt  = (float4*)smem_raw;                    // [NPX]
    uint32_t* pidx = (uint32_t*)(smem_raw + NPX * 16);     // [NPX]
    {
        const float* om_s = (const float*)(smem_raw + OFF_B);
        for (int i = tid; i < NPX; i += 256) {
            int tap = i / 56, pxx = i - tap * 56;
            float dy = om_s[tap * 64 + pxx];
            float dx = om_s[(K2 + tap) * 64 + pxx];
            float ml = om_s[(2 * K2 + tap) * 64 + pxx];
            float m  = 1.f / (1.f + __expf(-ml));
            float sy = (float)(y   + tap / K - P) + dy;
            float sx = (float)(pxx + tap % K - P) + dx;
            float y0f = floorf(sy), x0f = floorf(sx);
            float ty = sy - y0f, tx = sx - x0f;
            int y0 = (int)y0f, x0 = (int)x0f, y1 = y0 + 1, x1 = x0 + 1;
            bool vy0 = (y0 >= 0) && (y0 < HH), vy1 = (y1 >= 0) && (y1 < HH);
            bool vx0 = (x0 >= 0) && (x0 < WW), vx1 = (x1 >= 0) && (x1 < WW);
            float w00 = (vy0 && vx0) ? (1.f - ty) * (1.f - tx) * m : 0.f;
            float w01 = (vy0 && vx1) ? (1.f - ty) * tx * m : 0.f;
            float w10 = (vy1 && vx0) ? ty * (1.f - tx) * m : 0.f;
            float w11 = (vy1 && vx1) ? ty * tx * m : 0.f;
            int cy0 = min(max(y0, 0), HH - 1);
            int cy1 = min(max(y1, 0), HH - 1);
            int cx0 = min(max(x0, 0), WW - 1);
            int cx1 = min(max(x1, 0), WW - 1);
            uint32_t bb  = (uint32_t)(cy0 * WW + cx0);
            uint32_t ddx = (uint32_t)(cx1 - cx0);            // 0 or 1
            uint32_t ddy = (uint32_t)((cy1 - cy0) * WW);     // 0 or 56
            swt [i] = make_float4(w00, w01, w10, w11);
            pidx[i] = bb | (ddx << 16) | (ddy << 18);
        }
    }
    __syncthreads();   // om_s fully consumed; region B is free now

    // ======================= Phase B: deform conv ==========================
    float2* ws2   = (float2*)(smem_raw + OFF_B);                    // [2][64*K2]
    float*  cols  = (float*)(smem_raw + OFF_B + 64 * K2 * 16);      // [2][NPX]
    float*  xrow  = (float*)(smem_raw + OFF_C);                     // [2][64]
    float2* subw2 = (float2*)(smem_raw + OFF_C + 512);              // [2][64]

    auto fill = [&](int c, int buf) {
        const float* Xc = xb + c * HW;
        float* cb = cols + buf * NPX;
#pragma unroll
        for (int it = 0; it < NIT; it++) {
            int i = tid + it * 256;
            if (i < NPX) {
                uint32_t pv = pidx[i];
                float4 wv = swt[i];
                int base = pv & 0xFFFF;
                int ddx  = (pv >> 16) & 3;
                int ddy  = pv >> 18;
                cb[i] = wv.x * Xc[base]       + wv.y * Xc[base + ddx]
                      + wv.z * Xc[base + ddy] + wv.w * Xc[base + ddy + ddx];
            }
        }
        // vectorized contiguous weight copy
        {
            float4* dst = (float4*)(ws2 + buf * 64 * K2);
            const float4* src = (const float4*)(wp + c * 64 * K2);
#pragma unroll
            for (int it = 0; it < (WV4 + 255) / 256; it++) {
                int i = tid + it * 256;
                if (i < WV4) dst[i] = src[i];
            }
        }
        if (tid < 64) {
            xrow[buf * 64 + tid] = (tid < WW) ? Xc[y * WW + tid] : 0.f;
        } else if (tid < 96) {
            ((float4*)(subw2 + buf * 64))[tid - 64] =
                ((const float4*)((const float2*)g_swp + c * 64))[tid - 64];
        }
    };

    fill(0, 0);
    __syncthreads();

    u64 acc[16] = {};

    for (int c = 0; c < CIN; c++) {
        int cur = c & 1;
        if (c + 1 < CIN) fill(c + 1, cur ^ 1);

        const float* cc  = cols + cur * NPX;
        const u64* wrow  = (const u64*)(ws2 + cur * 64 * K2) + g * 8 * K2;
#pragma unroll
        for (int tap = 0; tap < K2; tap++) {
            float c0 = cc[tap * 56 + lane];
            float c1 = cc[tap * 56 + lane + 32];   // lanes >= 24: discarded (pad keeps in-bounds)
            u64 xa = pack2(c0, c0), xc = pack2(c1, c1);
#pragma unroll
            for (int j = 0; j < 8; j++) {
                u64 wv = wrow[j * K2 + tap];
                ffma2(acc[2 * j],     xa, wv);
                ffma2(acc[2 * j + 1], xc, wv);
            }
        }
        // fused 1x1 residual
        {
            float s0 = xrow[cur * 64 + lane], s1 = xrow[cur * 64 + lane + 32];
            u64 xa = pack2(s0, s0), xc = pack2(s1, s1);
            const u64* srow = (const u64*)(subw2 + cur * 64) + g * 8;
#pragma unroll
            for (int j = 0; j < 8; j++) {
                u64 sv = srow[j];
                ffma2(acc[2 * j],     xa, sv);
                ffma2(acc[2 * j + 1], xc, sv);
            }
        }
        __syncthreads();
    }

#pragma unroll
    for (int j = 0; j < 8; j++) {
        int o0 = g * 16 + 2 * j, o1 = o0 + 1;
        float2 v0 = unpack2(acc[2 * j]);
        float2 v1 = unpack2(acc[2 * j + 1]);
        float bb0 = bias[o0] + subb[o0];
        float bb1 = bias[o1] + subb[o1];
        size_t base0 = ((size_t)b * (2 * OCM) + CB + o0) * HW + y * WW;
        size_t base1 = ((size_t)b * (2 * OCM) + CB + o1) * HW + y * WW;
        out[base0 + lane] = fmaxf(v0.x + bb0, 0.f);
        out[base1 + lane] = fmaxf(v0.y + bb1, 0.f);
        if (lane + 32 < WW) {
            out[base0 + lane + 32] = fmaxf(v1.x + bb0, 0.f);
            out[base1 + lane + 32] = fmaxf(v1.y + bb1, 0.f);
        }
    }
}

static constexpr int fused_smem(int K) {
    int K2 = K * K, OCF = 3 * K2, NPX = K2 * 56;
    int NPT = (((OCF + 1) / 2) + 7) & ~7;
    int szA_off = NPT * K2 * 16 + 2 * K * 72 * 4;
    int szA_def = NPX * 20;
    int szA = ((szA_off > szA_def ? szA_off : szA_def) + 15) & ~15;
    int szB_off = OCF * 64 * 4;
    int szB_def = 64 * K2 * 16 + NPX * 8 + 64;
    int szB = ((szB_off > szB_def ? szB_off : szB_def) + 15) & ~15;
    return szA + szB + 512 + 1024;
}

// ---------------------------------------------------------------------------
// Side stream + fork/join events (created once at load; no device allocation).
// ---------------------------------------------------------------------------
struct Aux {
    cudaStream_t s1;
    cudaEvent_t  fork, join;
    Aux() {
        cudaStreamCreateWithFlags(&s1, cudaStreamNonBlocking);
        cudaEventCreateWithFlags(&fork, cudaEventDisableTiming);
        cudaEventCreateWithFlags(&join, cudaEventDisableTiming);
    }
};
static Aux g_aux;

extern "C" void kernel_launch(void* const* d_in, const int* in_sizes, int n_in,
                              void* d_out, int out_size)
{
    const float* x   = (const float*)d_in[0];
    const float* w3  = (const float*)d_in[1];
    const float* b3  = (const float*)d_in[2];
    const float* o3w = (const float*)d_in[3];
    const float* o3b = (const float*)d_in[4];
    const float* w5  = (const float*)d_in[5];
    const float* b5  = (const float*)d_in[6];
    const float* o5w = (const float*)d_in[7];
    const float* o5b = (const float*)d_in[8];
    const float* sw  = (const float*)d_in[9];
    const float* sb  = (const float*)d_in[10];
    float* out = (float*)d_out;

    constexpr int SM3 = fused_smem(3);   // ~24.9 KB
    constexpr int SM5 = fused_smem(5);   // ~66.4 KB -> 3 blocks/SM
    cudaFuncSetAttribute((const void*)fused_kernel<3, 0>,
                         cudaFuncAttributeMaxDynamicSharedMemorySize, SM3);
    cudaFuncSetAttribute((const void*)fused_kernel<5, OCM>,
                         cudaFuncAttributeMaxDynamicSharedMemorySize, SM5);

    dim3 grid(BN * HH);

    prep_weights<<<(CIN * 64 * 25 + 255) / 256, 256>>>(w3, w5, sw, o3w, o5w);

    cudaEventRecord(g_aux.fork, 0);
    cudaStreamWaitEvent(g_aux.s1, g_aux.fork, 0);

    // R10 order: k3 chain on side stream, k5 chain on main stream.
    fused_kernel<3, 0  ><<<grid, 256, SM3, g_aux.s1>>>(x, o3b, b3, sb, out);
    fused_kernel<5, OCM><<<grid, 256, SM5>>>(x, o5b, b5, sb, out);

    cudaEventRecord(g_aux.join, g_aux.s1);
    cudaStreamWaitEvent(0, g_aux.join, 0);
}